// round 3
// baseline (speedup 1.0000x reference)
#include <cuda_runtime.h>
#include <math.h>

#define HEADS 8
#define DH    64
#define NQ    4096
#define NK    1024
#define BATCH 2
#define D     512
#define DC    768
#define BH    (BATCH*HEADS)   // 16
#define MQ    (BATCH*NQ)      // 8192 rows of q
#define MK    (BATCH*NK)      // 2048 rows of k/v

typedef unsigned long long ull;

// ---------------- scratch (device globals; no allocation allowed) ----------------
__device__ float g_q[MQ*D];            // q projection fp32
__device__ float g_k[MK*D];            // k projection fp32
__device__ float g_v[MK*D];            // v projection fp32
__device__ float g_oattn[MQ*D];        // attention output (pre out-proj)
__device__ int   g_q8 [BH*NQ*16];      // [bh][n][w]   int packs q8 dims 4w..4w+3
__device__ int   g_k8t[BH*16*NK];      // [bh][w][j]   int packs k8 dims 4w..4w+3 of row j
__device__ int   g_v8t[BH*256*DH];     // [bh][w][d]   int packs v8 rows j=4w..4w+3 of dim d
__device__ float g_rowmax[BH*NQ];
__device__ float g_rowz  [BH*NQ];
__device__ int   g_maxbits[4];         // abs-max bits: 0:q 1:k 2:v 3:attn(=max 1/Z)

// ---------------- init ----------------
__global__ void init_kernel() {
    if (threadIdx.x < 4) g_maxbits[threadIdx.x] = 0;
}

// ---------------- packed fp32 helpers ----------------
__device__ __forceinline__ void ffma2(ull &c, ull a, ull b) {
    asm("fma.rn.f32x2 %0, %1, %2, %3;" : "=l"(c) : "l"(a), "l"(b), "l"(c));
}

// ---------------- fp32 GEMM with f32x2 packed FMA ----------------
// TM x 128 tile, BK=8, 256 threads, double-buffered smem.
// A-tile stored duplicated as {a,a} so the inner loop needs no packing MOVs.
// Optional fused per-tensor absmax (slot >= 0) and bias.
// blockIdx.z == 1 switches to (B1, C1, slot0+1) — used to fuse k & v projections.
template<int TM>
__global__ __launch_bounds__(256) void gemm_f2(
    const float* __restrict__ A, const float* __restrict__ B0,
    const float* __restrict__ B1, const float* __restrict__ bias,
    float* __restrict__ C0, float* __restrict__ C1,
    int M, int N, int K, int slot0)
{
    constexpr int RPT = TM / 16;   // rows per thread (8 for TM=128, 4 for TM=64)
    __shared__ __align__(16) float2 As2[2][8][TM];
    __shared__ __align__(16) float2 Bs2[2][8][64];
    __shared__ float red[8];

    const float* B = B0;
    float* C = C0;
    int slot = slot0;
    if (blockIdx.z == 1) { B = B1; C = C1; slot = slot0 + 1; }

    const int tid = threadIdx.x;
    const int tx  = tid & 15;
    const int ty  = tid >> 4;
    const int row0 = blockIdx.y * TM;
    const int col0 = blockIdx.x * 128;

    // loader indices
    const int arow = tid >> 1;          // TM=128: 0..127 ; TM=64: valid for tid<128
    const int akc  = (tid & 1) * 4;
    const int bk   = tid >> 5;          // 0..7
    const int bn   = (tid & 31) * 4;    // 0..124
    const bool aload = (TM == 128) || (tid < 128);

    ull acc[RPT][4];
    #pragma unroll
    for (int r = 0; r < RPT; r++)
        #pragma unroll
        for (int j = 0; j < 4; j++) acc[r][j] = 0ull;

    // prologue: tile k0 = 0 -> buffer 0
    {
        if (aload) {
            float4 a4 = *(const float4*)(A + (size_t)(row0 + arow) * K + akc);
            As2[0][akc + 0][arow] = make_float2(a4.x, a4.x);
            As2[0][akc + 1][arow] = make_float2(a4.y, a4.y);
            As2[0][akc + 2][arow] = make_float2(a4.z, a4.z);
            As2[0][akc + 3][arow] = make_float2(a4.w, a4.w);
        }
        float4 b4 = *(const float4*)(B + (size_t)bk * N + col0 + bn);
        *(float4*)(&Bs2[0][bk][bn >> 1]) = b4;
    }
    __syncthreads();

    int cur = 0;
    for (int k0 = 0; k0 < K; k0 += 8) {
        const int kn = k0 + 8;
        const bool has = kn < K;
        float4 a4, b4;
        if (has) {
            if (aload)
                a4 = *(const float4*)(A + (size_t)(row0 + arow) * K + kn + akc);
            b4 = *(const float4*)(B + (size_t)(kn + bk) * N + col0 + bn);
        }
        #pragma unroll
        for (int kk = 0; kk < 8; kk++) {
            ull a[RPT], b[4];
            const ull* bp = (const ull*)Bs2[cur][kk];
            #pragma unroll
            for (int j = 0; j < 4; j++) b[j] = bp[tx * 4 + j];
            const ull* ap = (const ull*)As2[cur][kk];
            #pragma unroll
            for (int r = 0; r < RPT; r++) a[r] = ap[ty * RPT + r];
            #pragma unroll
            for (int r = 0; r < RPT; r++)
                #pragma unroll
                for (int j = 0; j < 4; j++)
                    ffma2(acc[r][j], a[r], b[j]);
        }
        if (has) {
            const int nb = cur ^ 1;
            if (aload) {
                As2[nb][akc + 0][arow] = make_float2(a4.x, a4.x);
                As2[nb][akc + 1][arow] = make_float2(a4.y, a4.y);
                As2[nb][akc + 2][arow] = make_float2(a4.z, a4.z);
                As2[nb][akc + 3][arow] = make_float2(a4.w, a4.w);
            }
            *(float4*)(&Bs2[nb][bk][bn >> 1]) = b4;
            __syncthreads();
        }
        cur ^= 1;
    }

    // epilogue: store + fused absmax
    float amax = 0.0f;
    #pragma unroll
    for (int r = 0; r < RPT; r++) {
        const int row = row0 + ty * RPT + r;
        const int c   = col0 + tx * 8;
        float o[8];
        #pragma unroll
        for (int j = 0; j < 4; j++) {
            float2 f = *(float2*)&acc[r][j];
            o[2 * j]     = f.x;
            o[2 * j + 1] = f.y;
        }
        if (bias) {
            #pragma unroll
            for (int j = 0; j < 8; j++) o[j] += bias[c + j];
        }
        #pragma unroll
        for (int j = 0; j < 8; j++) amax = fmaxf(amax, fabsf(o[j]));
        float4 o0 = make_float4(o[0], o[1], o[2], o[3]);
        float4 o1 = make_float4(o[4], o[5], o[6], o[7]);
        *(float4*)(C + (size_t)row * N + c)     = o0;
        *(float4*)(C + (size_t)row * N + c + 4) = o1;
    }
    if (slot >= 0) {
        #pragma unroll
        for (int o = 16; o; o >>= 1)
            amax = fmaxf(amax, __shfl_xor_sync(0xffffffffu, amax, o));
        if ((tid & 31) == 0) red[tid >> 5] = amax;
        __syncthreads();
        if (tid == 0) {
            float mm = red[0];
            #pragma unroll
            for (int i = 1; i < 8; i++) mm = fmaxf(mm, red[i]);
            atomicMax(&g_maxbits[slot], __float_as_int(mm));
        }
    }
}

// ---------------- quantization helpers ----------------
__device__ __forceinline__ int quant1(float v, float invd) {
    int q = __float2int_rn(v * invd);       // round-to-nearest-even, matches jnp.round
    q = max(-128, min(127, q));
    return q & 0xff;
}
__device__ __forceinline__ int pack4(float a, float b, float c, float d, float invd) {
    return quant1(a, invd) | (quant1(b, invd) << 8) |
           (quant1(c, invd) << 16) | (quant1(d, invd) << 24);
}

// ---------------- quantize q: [bh][n][16 words of 4 dims] ----------------
__global__ void quant_q_kernel() {
    int tid = blockIdx.x * blockDim.x + threadIdx.x;   // BH*NQ*16 = 2^20
    int dw = tid & 15;
    int n  = (tid >> 4) & (NQ - 1);
    int bh = tid >> 16;
    int b = bh >> 3, h = bh & 7;
    float invd = 127.0f / __int_as_float(g_maxbits[0]);
    float4 v = *(const float4*)(g_q + ((size_t)(b * NQ + n) * D + h * DH + dw * 4));
    g_q8[tid] = pack4(v.x, v.y, v.z, v.w, invd);
}

// ---------------- quantize k transposed: [bh][w][j] ----------------
__global__ void quant_kT_kernel() {
    int tid = blockIdx.x * blockDim.x + threadIdx.x;   // BH*16*NK = 2^18
    int j  = tid & (NK - 1);
    int w  = (tid >> 10) & 15;
    int bh = tid >> 14;
    int b = bh >> 3, h = bh & 7;
    float invd = 127.0f / __int_as_float(g_maxbits[1]);
    float4 v = *(const float4*)(g_k + ((size_t)(b * NK + j) * D + h * DH + w * 4));
    g_k8t[tid] = pack4(v.x, v.y, v.z, v.w, invd);
}

// ---------------- quantize v transposed: [bh][w=j/4][d] ----------------
__global__ void quant_vT_kernel() {
    int tid = blockIdx.x * blockDim.x + threadIdx.x;   // BH*256*64 = 2^18
    int d  = tid & 63;
    int w  = (tid >> 6) & 255;
    int bh = tid >> 14;
    int b = bh >> 3, h = bh & 7;
    float invd = 127.0f / __int_as_float(g_maxbits[2]);
    int j0 = w * 4;
    float v0 = g_v[(size_t)(b * NK + j0 + 0) * D + h * DH + d];
    float v1 = g_v[(size_t)(b * NK + j0 + 1) * D + h * DH + d];
    float v2 = g_v[(size_t)(b * NK + j0 + 2) * D + h * DH + d];
    float v3 = g_v[(size_t)(b * NK + j0 + 3) * D + h * DH + d];
    g_v8t[tid] = pack4(v0, v1, v2, v3, invd);
}

// ---------------- attention pass 1: scores + softmax stats + global attn-max ----------------
__global__ __launch_bounds__(256) void attn_pass1() {
    const int lane = threadIdx.x & 31;
    const int warp = threadIdx.x >> 5;
    const int bh   = blockIdx.y;
    const int row  = blockIdx.x * 8 + warp;
    const float dq = __int_as_float(g_maxbits[0]) * (1.0f / 127.0f);
    const float dk = __int_as_float(g_maxbits[1]) * (1.0f / 127.0f);
    const float alpha = dq * dk * 0.125f;   // * dh^-0.5

    int q[16];
    const int* qr = g_q8 + ((size_t)bh * NQ + row) * 16;
    #pragma unroll
    for (int i = 0; i < 16; i++) q[i] = qr[i];

    const int* kb = g_k8t + (size_t)bh * 16 * NK;
    float sim[32];
    float rmax = -1e30f;
    #pragma unroll
    for (int t = 0; t < 8; t++) {
        int s0 = 0, s1 = 0, s2 = 0, s3 = 0;
        const int jbase = t * 128 + lane * 4;
        #pragma unroll
        for (int w = 0; w < 16; w++) {
            int4 kv = *(const int4*)(kb + w * NK + jbase);
            s0 = __dp4a(q[w], kv.x, s0);
            s1 = __dp4a(q[w], kv.y, s1);
            s2 = __dp4a(q[w], kv.z, s2);
            s3 = __dp4a(q[w], kv.w, s3);
        }
        sim[t * 4 + 0] = (float)s0 * alpha;
        sim[t * 4 + 1] = (float)s1 * alpha;
        sim[t * 4 + 2] = (float)s2 * alpha;
        sim[t * 4 + 3] = (float)s3 * alpha;
        rmax = fmaxf(rmax, fmaxf(fmaxf(sim[t*4], sim[t*4+1]), fmaxf(sim[t*4+2], sim[t*4+3])));
    }
    #pragma unroll
    for (int o = 16; o; o >>= 1) rmax = fmaxf(rmax, __shfl_xor_sync(0xffffffffu, rmax, o));
    float z = 0.0f;
    #pragma unroll
    for (int t = 0; t < 32; t++) z += expf(sim[t] - rmax);
    #pragma unroll
    for (int o = 16; o; o >>= 1) z += __shfl_xor_sync(0xffffffffu, z, o);

    __shared__ float s_m[8];
    if (lane == 0) {
        g_rowmax[(size_t)bh * NQ + row] = rmax;
        g_rowz  [(size_t)bh * NQ + row] = z;
        s_m[warp] = 1.0f / z;               // max attn prob of this row
    }
    __syncthreads();
    if (threadIdx.x == 0) {
        float mm = s_m[0];
        #pragma unroll
        for (int i = 1; i < 8; i++) mm = fmaxf(mm, s_m[i]);
        atomicMax(&g_maxbits[3], __float_as_int(mm));
    }
}

// ---------------- attention pass 2: recompute scores, quantize attn, int8 AV ----------------
__global__ __launch_bounds__(256) void attn_pass2() {
    __shared__ int s_aq[8][256];            // packed int8 attn weights per warp-row
    const int lane = threadIdx.x & 31;
    const int warp = threadIdx.x >> 5;
    const int bh   = blockIdx.y;
    const int row  = blockIdx.x * 8 + warp;
    const int b = bh >> 3, h = bh & 7;

    const float dq = __int_as_float(g_maxbits[0]) * (1.0f / 127.0f);
    const float dk = __int_as_float(g_maxbits[1]) * (1.0f / 127.0f);
    const float alpha = dq * dk * 0.125f;
    const float amax  = __int_as_float(g_maxbits[3]);
    const float da    = amax * (1.0f / 127.0f);
    const float dv    = __int_as_float(g_maxbits[2]) * (1.0f / 127.0f);
    const float rmax  = g_rowmax[(size_t)bh * NQ + row];
    const float escale = (1.0f / g_rowz[(size_t)bh * NQ + row]) * (127.0f / amax);

    int q[16];
    const int* qr = g_q8 + ((size_t)bh * NQ + row) * 16;
    #pragma unroll
    for (int i = 0; i < 16; i++) q[i] = qr[i];

    const int* kb = g_k8t + (size_t)bh * 16 * NK;
    #pragma unroll
    for (int t = 0; t < 8; t++) {
        int s0 = 0, s1 = 0, s2 = 0, s3 = 0;
        const int jbase = t * 128 + lane * 4;
        #pragma unroll
        for (int w = 0; w < 16; w++) {
            int4 kv = *(const int4*)(kb + w * NK + jbase);
            s0 = __dp4a(q[w], kv.x, s0);
            s1 = __dp4a(q[w], kv.y, s1);
            s2 = __dp4a(q[w], kv.z, s2);
            s3 = __dp4a(q[w], kv.w, s3);
        }
        int a0 = min(127, __float2int_rn(expf((float)s0 * alpha - rmax) * escale));
        int a1 = min(127, __float2int_rn(expf((float)s1 * alpha - rmax) * escale));
        int a2 = min(127, __float2int_rn(expf((float)s2 * alpha - rmax) * escale));
        int a3 = min(127, __float2int_rn(expf((float)s3 * alpha - rmax) * escale));
        s_aq[warp][t * 32 + lane] = a0 | (a1 << 8) | (a2 << 16) | (a3 << 24);
    }
    __syncwarp();

    const int* vb = g_v8t + (size_t)bh * 256 * DH;
    const int* aq = s_aq[warp];
    const float oscale = da * dv;
    #pragma unroll
    for (int dd = 0; dd < 2; dd++) {
        const int d = dd * 32 + lane;
        int acc = 0;
        #pragma unroll 8
        for (int w = 0; w < 256; w++)
            acc = __dp4a(aq[w], vb[w * DH + d], acc);
        g_oattn[((size_t)(b * NQ + row)) * D + h * DH + d] = (float)acc * oscale;
    }
}

// ---------------- launch ----------------
extern "C" void kernel_launch(void* const* d_in, const int* in_sizes, int n_in,
                              void* d_out, int out_size) {
    const float* x   = (const float*)d_in[0];
    const float* ctx = (const float*)d_in[1];
    const float* Wq  = (const float*)d_in[2];
    const float* Wk  = (const float*)d_in[3];
    const float* Wv  = (const float*)d_in[4];
    const float* Wo  = (const float*)d_in[5];
    const float* bo  = (const float*)d_in[6];
    float* out = (float*)d_out;

    void *pq, *pk, *pv, *po;
    cudaGetSymbolAddress(&pq, g_q);
    cudaGetSymbolAddress(&pk, g_k);
    cudaGetSymbolAddress(&pv, g_v);
    cudaGetSymbolAddress(&po, g_oattn);

    init_kernel<<<1, 32>>>();

    // projections (fp32-exact via f32x2 packed FMA; absmax fused into epilogue)
    gemm_f2<128><<<dim3(D / 128, MQ / 128), 256>>>(
        x, Wq, nullptr, nullptr, (float*)pq, nullptr, MQ, D, D, 0);
    gemm_f2<64><<<dim3(D / 128, MK / 64, 2), 256>>>(
        ctx, Wk, Wv, nullptr, (float*)pk, (float*)pv, MK, D, DC, 1);

    // int8 quantization (layouts tuned for coalesced dp4a streams)
    quant_q_kernel <<<(BH * NQ * 16) / 256, 256>>>();
    quant_kT_kernel<<<(BH * 16 * NK) / 256, 256>>>();
    quant_vT_kernel<<<(BH * 256 * DH) / 256, 256>>>();

    // attention: exact int8 scores, softmax stats + global attn max, then quantized AV
    attn_pass1<<<dim3(NQ / 8, BH), 256>>>();
    attn_pass2<<<dim3(NQ / 8, BH), 256>>>();

    // output projection + bias
    gemm_f2<128><<<dim3(D / 128, MQ / 128), 256>>>(
        (const float*)po, Wo, nullptr, bo, out, nullptr, MQ, D, D, -1);
}

// round 9
// speedup vs baseline: 1.3470x; 1.3470x over previous
#include <cuda_runtime.h>
#include <math.h>
#include <stdint.h>

#define HEADS 8
#define DH    64
#define NQ    4096
#define NK    1024
#define BATCH 2
#define D     512
#define DC    768
#define BH    (BATCH*HEADS)   // 16
#define MQ    (BATCH*NQ)      // 8192
#define MK    (BATCH*NK)      // 2048

// ---------------- scratch (device globals; no allocation allowed) ----------------
__device__ float g_q[MQ*D];
__device__ float g_k[MK*D];
__device__ float g_v[MK*D];
__device__ float g_oattn[MQ*D];
__device__ float g_p[(size_t)BH*NQ*NK];   // exp(sim - rowmax), 256MB
__device__ int   g_q8 [BH*NQ*16];         // [bh][n][w]  w packs dims 4w..4w+3
__device__ int   g_k8t[BH*16*NK];         // [bh][w][j]
__device__ int   g_v8t[BH*256*DH];        // [bh][w=j/4][d]
__device__ float g_rowz[BH*NQ];
__device__ int   g_maxbits[4];            // 0:q 1:k 2:v 3:attn(max 1/Z)

__global__ void init_kernel() {
    if (threadIdx.x < 4) g_maxbits[threadIdx.x] = 0;
}

// ---------------- fp32 GEMM (known-good from R2): 128x128 tile, BK=8 ----------------
__global__ __launch_bounds__(256) void gemm128(
    const float* __restrict__ A, const float* __restrict__ B,
    const float* __restrict__ bias, float* __restrict__ C,
    int M, int N, int K)
{
    __shared__ float As[8][128];
    __shared__ float Bs[8][128];
    const int tid  = threadIdx.x;
    const int tx   = tid & 15;
    const int ty   = tid >> 4;
    const int row0 = blockIdx.y * 128;
    const int col0 = blockIdx.x * 128;

    const int am = tid >> 1;
    const int ak = (tid & 1) * 4;
    const int bk = tid >> 5;
    const int bn = (tid & 31) * 4;

    float acc[8][8];
    #pragma unroll
    for (int i = 0; i < 8; i++)
        #pragma unroll
        for (int j = 0; j < 8; j++) acc[i][j] = 0.0f;

    for (int k0 = 0; k0 < K; k0 += 8) {
        float4 a4 = *(const float4*)(A + (size_t)(row0 + am) * K + k0 + ak);
        float4 b4 = *(const float4*)(B + (size_t)(k0 + bk) * N + col0 + bn);
        As[ak + 0][am] = a4.x;
        As[ak + 1][am] = a4.y;
        As[ak + 2][am] = a4.z;
        As[ak + 3][am] = a4.w;
        *(float4*)(&Bs[bk][bn]) = b4;
        __syncthreads();
        #pragma unroll
        for (int kk = 0; kk < 8; kk++) {
            float4 a0 = *(const float4*)(&As[kk][ty * 8]);
            float4 a1 = *(const float4*)(&As[kk][ty * 8 + 4]);
            float4 b0 = *(const float4*)(&Bs[kk][tx * 8]);
            float4 b1 = *(const float4*)(&Bs[kk][tx * 8 + 4]);
            float a[8] = {a0.x, a0.y, a0.z, a0.w, a1.x, a1.y, a1.z, a1.w};
            float b[8] = {b0.x, b0.y, b0.z, b0.w, b1.x, b1.y, b1.z, b1.w};
            #pragma unroll
            for (int i = 0; i < 8; i++)
                #pragma unroll
                for (int j = 0; j < 8; j++)
                    acc[i][j] = fmaf(a[i], b[j], acc[i][j]);
        }
        __syncthreads();
    }

    #pragma unroll
    for (int i = 0; i < 8; i++) {
        const int r = row0 + ty * 8 + i;
        #pragma unroll
        for (int j = 0; j < 8; j += 4) {
            const int c = col0 + tx * 8 + j;
            float4 o;
            o.x = acc[i][j + 0];
            o.y = acc[i][j + 1];
            o.z = acc[i][j + 2];
            o.w = acc[i][j + 3];
            if (bias) {
                o.x += bias[c + 0]; o.y += bias[c + 1];
                o.z += bias[c + 2]; o.w += bias[c + 3];
            }
            *(float4*)(C + (size_t)r * N + c) = o;
        }
    }
}

// ---------------- abs-max reduction ----------------
__global__ void absmax_kernel(const float* __restrict__ x, int n, int slot) {
    float m = 0.0f;
    for (int i = blockIdx.x * blockDim.x + threadIdx.x; i < n; i += gridDim.x * blockDim.x)
        m = fmaxf(m, fabsf(x[i]));
    #pragma unroll
    for (int o = 16; o; o >>= 1) m = fmaxf(m, __shfl_xor_sync(0xffffffffu, m, o));
    __shared__ float sm[8];
    if ((threadIdx.x & 31) == 0) sm[threadIdx.x >> 5] = m;
    __syncthreads();
    if (threadIdx.x == 0) {
        float mm = sm[0];
        #pragma unroll
        for (int i = 1; i < 8; i++) mm = fmaxf(mm, sm[i]);
        atomicMax(&g_maxbits[slot], __float_as_int(mm));
    }
}

// ---------------- quantization ----------------
__device__ __forceinline__ int quant1(float v, float invd) {
    int q = __float2int_rn(v * invd);
    q = max(-128, min(127, q));
    return q & 0xff;
}
__device__ __forceinline__ int pack4(float a, float b, float c, float d, float invd) {
    return quant1(a, invd) | (quant1(b, invd) << 8) |
           (quant1(c, invd) << 16) | (quant1(d, invd) << 24);
}

__global__ void quant_q_kernel() {
    int tid = blockIdx.x * blockDim.x + threadIdx.x;
    int dw = tid & 15;
    int n  = (tid >> 4) & (NQ - 1);
    int bh = tid >> 16;
    int b = bh >> 3, h = bh & 7;
    float invd = 127.0f / __int_as_float(g_maxbits[0]);
    float4 v = *(const float4*)(g_q + ((size_t)(b * NQ + n) * D + h * DH + dw * 4));
    g_q8[tid] = pack4(v.x, v.y, v.z, v.w, invd);
}
__global__ void quant_kT_kernel() {
    int tid = blockIdx.x * blockDim.x + threadIdx.x;
    int j  = tid & (NK - 1);
    int w  = (tid >> 10) & 15;
    int bh = tid >> 14;
    int b = bh >> 3, h = bh & 7;
    float invd = 127.0f / __int_as_float(g_maxbits[1]);
    float4 v = *(const float4*)(g_k + ((size_t)(b * NK + j) * D + h * DH + w * 4));
    g_k8t[tid] = pack4(v.x, v.y, v.z, v.w, invd);
}
__global__ void quant_vT_kernel() {
    int tid = blockIdx.x * blockDim.x + threadIdx.x;
    int d  = tid & 63;
    int w  = (tid >> 6) & 255;
    int bh = tid >> 14;
    int b = bh >> 3, h = bh & 7;
    float invd = 127.0f / __int_as_float(g_maxbits[2]);
    int j0 = w * 4;
    float v0 = g_v[(size_t)(b * NK + j0 + 0) * D + h * DH + d];
    float v1 = g_v[(size_t)(b * NK + j0 + 1) * D + h * DH + d];
    float v2 = g_v[(size_t)(b * NK + j0 + 2) * D + h * DH + d];
    float v3 = g_v[(size_t)(b * NK + j0 + 3) * D + h * DH + d];
    g_v8t[tid] = pack4(v0, v1, v2, v3, invd);
}

// ---------------- int8 mma.sync m16n8k32 ----------------
__device__ __forceinline__ void imma(int* c, int a0, int a1, int a2, int a3,
                                     int b0, int b1) {
    asm volatile(
        "mma.sync.aligned.m16n8k32.row.col.s32.s8.s8.s32 "
        "{%0,%1,%2,%3}, {%4,%5,%6,%7}, {%8,%9}, {%0,%1,%2,%3};"
        : "+r"(c[0]), "+r"(c[1]), "+r"(c[2]), "+r"(c[3])
        : "r"(a0), "r"(a1), "r"(a2), "r"(a3), "r"(b0), "r"(b1));
}

// ======== attention pass 1 (IMMA): scores, rowmax, p=exp, Z, global attn-max ========
// Grid (NQ/128, BH), 256 thr. Warp w -> 16 q rows. K tile (64KB) in smem, padded.
#define K8S_STRIDE 1032
#define P1_SMEM (16 * K8S_STRIDE * 4)

__global__ __launch_bounds__(256) void attn_pass1() {
    extern __shared__ int k8s[];              // [16][1032]
    __shared__ float s_m[8];
    const int tid  = threadIdx.x;
    const int lane = tid & 31;
    const int warp = tid >> 5;
    const int bh   = blockIdx.y;
    const int Rw   = blockIdx.x * 128 + warp * 16;

    // stage k8 tile (16 word-rows x 1024 j), padded stride for conflict-free B-frags
    const int4* src = (const int4*)(g_k8t + (size_t)bh * 16 * NK);
    #pragma unroll
    for (int i = 0; i < 16; i++) {
        int idx = i * 256 + tid;              // int4 index, 4096 total
        int w  = idx >> 8;
        int j4 = idx & 255;
        *(int4*)(k8s + w * K8S_STRIDE + j4 * 4) = src[idx];
    }
    __syncthreads();

    const float dq = __int_as_float(g_maxbits[0]) * (1.0f / 127.0f);
    const float dk = __int_as_float(g_maxbits[1]) * (1.0f / 127.0f);
    const float alpha = dq * dk * 0.125f;     // * dh^-0.5

    // hoist A fragments (q8)
    const int r0 = Rw + (lane >> 2);
    const int* q0 = g_q8 + ((size_t)bh * NQ + r0) * 16;
    const int* q1 = q0 + 8 * 16;
    int a[2][4];
    #pragma unroll
    for (int ks = 0; ks < 2; ks++) {
        a[ks][0] = q0[ks * 8 + (lane & 3)];
        a[ks][1] = q1[ks * 8 + (lane & 3)];
        a[ks][2] = q0[ks * 8 + 4 + (lane & 3)];
        a[ks][3] = q1[ks * 8 + 4 + (lane & 3)];
    }

    // ---- sweep 1: integer row maxima (alpha > 0 => monotone) ----
    int m0i = -2147483647, m1i = -2147483647;
    for (int jb = 0; jb < 128; jb++) {
        int c[4] = {0, 0, 0, 0};
        #pragma unroll
        for (int ks = 0; ks < 2; ks++) {
            int b0 = k8s[(ks * 8 + (lane & 3)) * K8S_STRIDE + jb * 8 + (lane >> 2)];
            int b1 = k8s[(ks * 8 + 4 + (lane & 3)) * K8S_STRIDE + jb * 8 + (lane >> 2)];
            imma(c, a[ks][0], a[ks][1], a[ks][2], a[ks][3], b0, b1);
        }
        m0i = max(m0i, max(c[0], c[1]));
        m1i = max(m1i, max(c[2], c[3]));
    }
    m0i = max(m0i, __shfl_xor_sync(0xffffffffu, m0i, 1));
    m0i = max(m0i, __shfl_xor_sync(0xffffffffu, m0i, 2));
    m1i = max(m1i, __shfl_xor_sync(0xffffffffu, m1i, 1));
    m1i = max(m1i, __shfl_xor_sync(0xffffffffu, m1i, 2));

    // ---- sweep 2: recompute scores, p = exp(alpha*(c-mi)), accumulate Z, store p ----
    float* pr0 = g_p + ((size_t)bh * NQ + r0) * NK;
    float* pr1 = pr0 + (size_t)8 * NK;
    float z0 = 0.0f, z1 = 0.0f;
    for (int jb = 0; jb < 128; jb++) {
        int c[4] = {0, 0, 0, 0};
        #pragma unroll
        for (int ks = 0; ks < 2; ks++) {
            int b0 = k8s[(ks * 8 + (lane & 3)) * K8S_STRIDE + jb * 8 + (lane >> 2)];
            int b1 = k8s[(ks * 8 + 4 + (lane & 3)) * K8S_STRIDE + jb * 8 + (lane >> 2)];
            imma(c, a[ks][0], a[ks][1], a[ks][2], a[ks][3], b0, b1);
        }
        float e00 = expf((float)(c[0] - m0i) * alpha);
        float e01 = expf((float)(c[1] - m0i) * alpha);
        float e10 = expf((float)(c[2] - m1i) * alpha);
        float e11 = expf((float)(c[3] - m1i) * alpha);
        z0 += e00 + e01;
        z1 += e10 + e11;
        const int col = jb * 8 + 2 * (lane & 3);
        *(float2*)(pr0 + col) = make_float2(e00, e01);
        *(float2*)(pr1 + col) = make_float2(e10, e11);
    }
    z0 += __shfl_xor_sync(0xffffffffu, z0, 1);
    z0 += __shfl_xor_sync(0xffffffffu, z0, 2);
    z1 += __shfl_xor_sync(0xffffffffu, z1, 1);
    z1 += __shfl_xor_sync(0xffffffffu, z1, 2);

    if ((lane & 3) == 0) {
        g_rowz[(size_t)bh * NQ + r0]     = z0;
        g_rowz[(size_t)bh * NQ + r0 + 8] = z1;
    }
    // global max attn prob = max over rows of 1/Z
    float inv = fmaxf(1.0f / z0, 1.0f / z1);
    #pragma unroll
    for (int o = 16; o; o >>= 1) inv = fmaxf(inv, __shfl_xor_sync(0xffffffffu, inv, o));
    if (lane == 0) s_m[warp] = inv;
    __syncthreads();
    if (tid == 0) {
        float mm = s_m[0];
        #pragma unroll
        for (int i = 1; i < 8; i++) mm = fmaxf(mm, s_m[i]);
        atomicMax(&g_maxbits[3], __float_as_int(mm));
    }
}

// ======== attention pass 2 (IMMA): quantize stored p, int8 AV ========
// Grid (NQ/128, BH), 256 thr. V tile transposed [d][w] in smem; per-warp attn
// int8 chunks staged in smem for A-fragment loads.
#define V8S_STRIDE 260
#define AQ_STRIDE  68
#define P2_V_INTS  (64 * V8S_STRIDE)
#define P2_SMEM    ((P2_V_INTS + 8 * 16 * AQ_STRIDE) * 4)

__global__ __launch_bounds__(256) void attn_pass2() {
    extern __shared__ int sm2[];
    int* v8s = sm2;                       // [64][260] (d, j-word)
    int* aqb = sm2 + P2_V_INTS;           // [8 warps][16 rows][68]
    const int tid  = threadIdx.x;
    const int lane = tid & 31;
    const int warp = tid >> 5;
    const int bh   = blockIdx.y;
    const int Rw   = blockIdx.x * 128 + warp * 16;
    const int b = bh >> 3, h = bh & 7;

    // stage v8 transposed: src [w][d] -> v8s[d][w]
    const int* vsrc = g_v8t + (size_t)bh * 256 * DH;
    #pragma unroll
    for (int i = 0; i < 64; i++) {
        int idx = i * 256 + tid;
        int w = idx >> 6, d = idx & 63;
        v8s[d * V8S_STRIDE + w] = vsrc[idx];
    }
    __syncthreads();

    const float amax = __int_as_float(g_maxbits[3]);
    const float da   = amax * (1.0f / 127.0f);
    const float dv   = __int_as_float(g_maxbits[2]) * (1.0f / 127.0f);

    // quantizer mapping: thread -> row (lane>>1), j-half (lane&1)
    const int rloc = lane >> 1;
    const float rz = g_rowz[(size_t)bh * NQ + Rw + rloc];
    const float escale = (127.0f / amax) / rz;
    const float* prow = g_p + ((size_t)bh * NQ + Rw + rloc) * NK + (lane & 1) * 128;

    int acc[8][4];
    #pragma unroll
    for (int i = 0; i < 8; i++)
        #pragma unroll
        for (int j = 0; j < 4; j++) acc[i][j] = 0;

    int* aqw = aqb + warp * 16 * AQ_STRIDE;

    for (int ch = 0; ch < 4; ch++) {
        // quantize 256 j per row (this thread: 1 row x 128 j)
        const float* pp = prow + ch * 256;
        int* dst = aqw + rloc * AQ_STRIDE + (lane & 1) * 32;
        #pragma unroll
        for (int g = 0; g < 32; g++) {
            float4 pv = *(const float4*)(pp + g * 4);
            int a0 = min(127, __float2int_rn(pv.x * escale));
            int a1 = min(127, __float2int_rn(pv.y * escale));
            int a2 = min(127, __float2int_rn(pv.z * escale));
            int a3 = min(127, __float2int_rn(pv.w * escale));
            dst[g] = a0 | (a1 << 8) | (a2 << 16) | (a3 << 24);
        }
        __syncwarp();

        #pragma unroll
        for (int js = 0; js < 8; js++) {
            int a0 = aqw[(lane >> 2) * AQ_STRIDE + js * 8 + (lane & 3)];
            int a1 = aqw[((lane >> 2) + 8) * AQ_STRIDE + js * 8 + (lane & 3)];
            int a2 = aqw[(lane >> 2) * AQ_STRIDE + js * 8 + 4 + (lane & 3)];
            int a3 = aqw[((lane >> 2) + 8) * AQ_STRIDE + js * 8 + 4 + (lane & 3)];
            const int wbase = ch * 64 + js * 8;
            #pragma unroll
            for (int db = 0; db < 8; db++) {
                int b0 = v8s[(db * 8 + (lane >> 2)) * V8S_STRIDE + wbase + (lane & 3)];
                int b1 = v8s[(db * 8 + (lane >> 2)) * V8S_STRIDE + wbase + 4 + (lane & 3)];
                imma(acc[db], a0, a1, a2, a3, b0, b1);
            }
        }
        __syncwarp();
    }

    // epilogue
    const float oscale = da * dv;
    const int r = Rw + (lane >> 2);
    float* o0 = g_oattn + ((size_t)(b * NQ) + r) * D + h * DH;
    float* o1 = o0 + (size_t)8 * D;
    #pragma unroll
    for (int db = 0; db < 8; db++) {
        const int col = db * 8 + 2 * (lane & 3);
        *(float2*)(o0 + col) = make_float2((float)acc[db][0] * oscale,
                                           (float)acc[db][1] * oscale);
        *(float2*)(o1 + col) = make_float2((float)acc[db][2] * oscale,
                                           (float)acc[db][3] * oscale);
    }
}

// ================= launch =================
extern "C" void kernel_launch(void* const* d_in, const int* in_sizes, int n_in,
                              void* d_out, int out_size) {
    const float* x   = (const float*)d_in[0];
    const float* ctx = (const float*)d_in[1];
    const float* Wq  = (const float*)d_in[2];
    const float* Wk  = (const float*)d_in[3];
    const float* Wv  = (const float*)d_in[4];
    const float* Wo  = (const float*)d_in[5];
    const float* bo  = (const float*)d_in[6];
    float* out = (float*)d_out;

    void *pq, *pk, *pv, *po;
    cudaGetSymbolAddress(&pq, g_q);
    cudaGetSymbolAddress(&pk, g_k);
    cudaGetSymbolAddress(&pv, g_v);
    cudaGetSymbolAddress(&po, g_oattn);

    cudaFuncSetAttribute(attn_pass1, cudaFuncAttributeMaxDynamicSharedMemorySize, P1_SMEM);
    cudaFuncSetAttribute(attn_pass2, cudaFuncAttributeMaxDynamicSharedMemorySize, P2_SMEM);

    init_kernel<<<1, 32>>>();

    gemm128<<<dim3(D / 128, MQ / 128), 256>>>(x,   Wq, nullptr, (float*)pq, MQ, D, D);
    gemm128<<<dim3(D / 128, MK / 128), 256>>>(ctx, Wk, nullptr, (float*)pk, MK, D, DC);
    gemm128<<<dim3(D / 128, MK / 128), 256>>>(ctx, Wv, nullptr, (float*)pv, MK, D, DC);

    absmax_kernel<<<512, 256>>>((const float*)pq, MQ * D, 0);
    absmax_kernel<<<256, 256>>>((const float*)pk, MK * D, 1);
    absmax_kernel<<<256, 256>>>((const float*)pv, MK * D, 2);

    quant_q_kernel <<<(BH * NQ * 16) / 256, 256>>>();
    quant_kT_kernel<<<(BH * 16 * NK) / 256, 256>>>();
    quant_vT_kernel<<<(BH * 256 * DH) / 256, 256>>>();

    attn_pass1<<<dim3(NQ / 128, BH), 256, P1_SMEM>>>();
    attn_pass2<<<dim3(NQ / 128, BH), 256, P2_SMEM>>>();

    gemm128<<<dim3(D / 128, MQ / 128), 256>>>((const float*)po, Wo, bo, out, MQ, D, D);
}

// round 10
// speedup vs baseline: 2.5047x; 1.8595x over previous
#include <cuda_runtime.h>
#include <math.h>
#include <stdint.h>

#define HEADS 8
#define DH    64
#define NQ    4096
#define NK    1024
#define BATCH 2
#define D     512
#define DC    768
#define BH    (BATCH*HEADS)   // 16
#define MQ    (BATCH*NQ)      // 8192
#define MK    (BATCH*NK)      // 2048

// ---------------- scratch (device globals; no allocation allowed) ----------------
__device__ float g_q[MQ*D];
__device__ float g_k[MK*D];
__device__ float g_v[MK*D];
__device__ float g_oattn[MQ*D];
__device__ float g_p[(size_t)BH*NQ*NK];   // exp(sim - rowmax), 256MB
__device__ int   g_q8 [BH*NQ*16];         // [bh][n][w]  w packs dims 4w..4w+3
__device__ int   g_k8t[BH*16*NK];         // [bh][w][j]
__device__ int   g_v8t[BH*256*DH];        // [bh][w=j/4][d]
__device__ float g_rowz[BH*NQ];
__device__ int   g_maxbits[4];            // 0:q 1:k 2:v 3:attn(max 1/Z)

__global__ void init_kernel() {
    if (threadIdx.x < 4) g_maxbits[threadIdx.x] = 0;
}

__device__ __forceinline__ uint32_t smem_u32(const void* p) {
    uint32_t a;
    asm("{ .reg .u64 t; cvta.to.shared.u64 t, %1; cvt.u32.u64 %0, t; }" : "=r"(a) : "l"(p));
    return a;
}

// ---------------- mma.sync primitives (sm_80 baseline, legal on plain sm_103) ----------------
__device__ __forceinline__ void ldsm4(uint32_t* r, uint32_t addr) {
    asm volatile("ldmatrix.sync.aligned.m8n8.x4.shared.b16 {%0,%1,%2,%3}, [%4];"
        : "=r"(r[0]), "=r"(r[1]), "=r"(r[2]), "=r"(r[3]) : "r"(addr));
}
__device__ __forceinline__ void ldsm4t(uint32_t* r, uint32_t addr) {
    asm volatile("ldmatrix.sync.aligned.m8n8.x4.trans.shared.b16 {%0,%1,%2,%3}, [%4];"
        : "=r"(r[0]), "=r"(r[1]), "=r"(r[2]), "=r"(r[3]) : "r"(addr));
}
__device__ __forceinline__ void hmma(float* c, const uint32_t* a, const uint32_t* b) {
    asm volatile(
        "mma.sync.aligned.m16n8k16.row.col.f32.bf16.bf16.f32 "
        "{%0,%1,%2,%3}, {%4,%5,%6,%7}, {%8,%9}, {%0,%1,%2,%3};"
        : "+f"(c[0]), "+f"(c[1]), "+f"(c[2]), "+f"(c[3])
        : "r"(a[0]), "r"(a[1]), "r"(a[2]), "r"(a[3]), "r"(b[0]), "r"(b[1]));
}

// 2-way bf16 split of an fp32 pair: u1 = bf16x2(hi parts), u2 = bf16x2(residuals).
__device__ __forceinline__ void split2(float f0, float f1, uint32_t &u1, uint32_t &u2) {
    asm("cvt.rn.bf16x2.f32 %0, %1, %2;" : "=r"(u1) : "f"(f1), "f"(f0));
    float r0 = f0 - __uint_as_float(u1 << 16);
    float r1 = f1 - __uint_as_float(u1 & 0xffff0000u);
    asm("cvt.rn.bf16x2.f32 %0, %1, %2;" : "=r"(u2) : "f"(r1), "f"(r0));
}

// ================= bf16 split-GEMM (tensor pipe): C = A @ B (+bias), fused absmax =================
// CTA 128x128, 256 thr (8 warps: 4 m x 2 n blocks of 32x64), K-chunk 32, double buffered.
// A smem: [128 m][32 k] bf16, row stride 80B; B smem: [32 k][128 n] bf16, row stride 272B.
// Two splits each; products a1b1, a1b2, a2b1 recover ~2^-17 relative accuracy.
#define ASPLIT 10240                    // 128 * 80
#define BSPLIT 8704                     // 32 * 272
#define GB_BUF (2*ASPLIT + 2*BSPLIT)    // 37888
#define GB_SMEM (2*GB_BUF)              // 75776

__global__ __launch_bounds__(256) void gemm_bf3(
    const float* __restrict__ A, const float* __restrict__ B0,
    const float* __restrict__ B1, const float* __restrict__ bias,
    float* __restrict__ C0, float* __restrict__ C1,
    int M, int N, int K, int slot0)
{
    extern __shared__ __align__(128) char smem[];
    __shared__ float red[8];
    const int tid  = threadIdx.x;
    const int lane = tid & 31;
    const int warp = tid >> 5;

    const float* B = B0;
    float* C = C0;
    int slot = slot0;
    if (blockIdx.z == 1) { B = B1; C = C1; slot = slot0 + 1; }

    const int row0 = blockIdx.y * 128;
    const int col0 = blockIdx.x * 128;
    const uint32_t sb = smem_u32(smem);

    const int lam = tid >> 1, lak = (tid & 1) * 16;
    const int lbk = tid >> 3, lbn = (tid & 7) * 16;
    const float* gA = A + (size_t)(row0 + lam) * K + lak;
    const float* gB = B + (size_t)lbk * N + col0 + lbn;
    char* sA0 = smem + lam * 80 + lak * 2;
    char* sB0 = smem + 2 * ASPLIT + lbk * 272 + lbn * 2;

    const uint32_t aLane = (uint32_t)((lane & 15) * 80 + (lane >> 4) * 16 + (warp & 3) * 2560);
    const uint32_t bLane = (uint32_t)((lane & 15) * 272 + (lane >> 4) * 16 + (warp >> 2) * 128 + 2 * ASPLIT);

    float acc[2][8][4];
    #pragma unroll
    for (int i = 0; i < 2; i++)
        #pragma unroll
        for (int j = 0; j < 8; j++)
            #pragma unroll
            for (int t = 0; t < 4; t++) acc[i][j][t] = 0.0f;

    float4 va[4], vb[4];
    #pragma unroll
    for (int i = 0; i < 4; i++) va[i] = *(const float4*)(gA + i * 4);
    #pragma unroll
    for (int i = 0; i < 4; i++) vb[i] = *(const float4*)(gB + i * 4);
    #pragma unroll
    for (int i = 0; i < 4; i++) {
        uint32_t u1, u2;
        split2(va[i].x, va[i].y, u1, u2);
        *(uint32_t*)(sA0 + i * 8)              = u1;
        *(uint32_t*)(sA0 + i * 8 + ASPLIT)     = u2;
        split2(va[i].z, va[i].w, u1, u2);
        *(uint32_t*)(sA0 + i * 8 + 4)          = u1;
        *(uint32_t*)(sA0 + i * 8 + 4 + ASPLIT) = u2;
        split2(vb[i].x, vb[i].y, u1, u2);
        *(uint32_t*)(sB0 + i * 8)              = u1;
        *(uint32_t*)(sB0 + i * 8 + BSPLIT)     = u2;
        split2(vb[i].z, vb[i].w, u1, u2);
        *(uint32_t*)(sB0 + i * 8 + 4)          = u1;
        *(uint32_t*)(sB0 + i * 8 + 4 + BSPLIT) = u2;
    }
    __syncthreads();

    int buf = 0;
    for (int kc = 0; ; kc += 32) {
        const bool has = (kc + 32) < K;
        if (has) {
            gA += 32;
            gB += (size_t)32 * N;
            #pragma unroll
            for (int i = 0; i < 4; i++) va[i] = *(const float4*)(gA + i * 4);
            #pragma unroll
            for (int i = 0; i < 4; i++) vb[i] = *(const float4*)(gB + i * 4);
        }
        const uint32_t abase = sb + buf * GB_BUF + aLane;
        const uint32_t bbase = sb + buf * GB_BUF + bLane;
        #pragma unroll
        for (int k16 = 0; k16 < 2; k16++) {
            uint32_t af[2][2][4];
            #pragma unroll
            for (int s = 0; s < 2; s++)
                #pragma unroll
                for (int i = 0; i < 2; i++)
                    ldsm4(af[s][i], abase + s * ASPLIT + i * 1280 + k16 * 32);
            uint32_t bfr[2][4][4];
            #pragma unroll
            for (int t = 0; t < 2; t++)
                #pragma unroll
                for (int nt = 0; nt < 4; nt++)
                    ldsm4t(bfr[t][nt], bbase + t * BSPLIT + k16 * 4352 + nt * 32);
            #pragma unroll
            for (int p = 0; p < 3; p++) {
                const int sa  = (p == 2) ? 1 : 0;
                const int sbl = (p == 1) ? 1 : 0;
                #pragma unroll
                for (int i = 0; i < 2; i++)
                    #pragma unroll
                    for (int j = 0; j < 8; j++)
                        hmma(acc[i][j], af[sa][i], &bfr[sbl][j >> 1][(j & 1) * 2]);
            }
        }
        if (!has) break;
        char* dA = sA0 + (buf ^ 1) * GB_BUF;
        char* dB = sB0 + (buf ^ 1) * GB_BUF;
        #pragma unroll
        for (int i = 0; i < 4; i++) {
            uint32_t u1, u2;
            split2(va[i].x, va[i].y, u1, u2);
            *(uint32_t*)(dA + i * 8)              = u1;
            *(uint32_t*)(dA + i * 8 + ASPLIT)     = u2;
            split2(va[i].z, va[i].w, u1, u2);
            *(uint32_t*)(dA + i * 8 + 4)          = u1;
            *(uint32_t*)(dA + i * 8 + 4 + ASPLIT) = u2;
            split2(vb[i].x, vb[i].y, u1, u2);
            *(uint32_t*)(dB + i * 8)              = u1;
            *(uint32_t*)(dB + i * 8 + BSPLIT)     = u2;
            split2(vb[i].z, vb[i].w, u1, u2);
            *(uint32_t*)(dB + i * 8 + 4)          = u1;
            *(uint32_t*)(dB + i * 8 + 4 + BSPLIT) = u2;
        }
        __syncthreads();
        buf ^= 1;
    }

    const int rowbase = row0 + (warp & 3) * 32;
    const int colbase = col0 + (warp >> 2) * 64;
    float amax = 0.0f;
    #pragma unroll
    for (int i = 0; i < 2; i++) {
        const int r = rowbase + i * 16 + (lane >> 2);
        #pragma unroll
        for (int j = 0; j < 8; j++) {
            const int c = colbase + j * 8 + 2 * (lane & 3);
            float2 v0 = make_float2(acc[i][j][0], acc[i][j][1]);
            float2 v1 = make_float2(acc[i][j][2], acc[i][j][3]);
            if (bias) {
                float2 bv = *(const float2*)(bias + c);
                v0.x += bv.x; v0.y += bv.y;
                v1.x += bv.x; v1.y += bv.y;
            }
            amax = fmaxf(amax, fmaxf(fmaxf(fabsf(v0.x), fabsf(v0.y)),
                                     fmaxf(fabsf(v1.x), fabsf(v1.y))));
            *(float2*)(C + (size_t)r * N + c)       = v0;
            *(float2*)(C + (size_t)(r + 8) * N + c) = v1;
        }
    }
    if (slot >= 0) {
        #pragma unroll
        for (int o = 16; o; o >>= 1)
            amax = fmaxf(amax, __shfl_xor_sync(0xffffffffu, amax, o));
        if (lane == 0) red[warp] = amax;
        __syncthreads();
        if (tid == 0) {
            float mm = red[0];
            #pragma unroll
            for (int i = 1; i < 8; i++) mm = fmaxf(mm, red[i]);
            atomicMax(&g_maxbits[slot], __float_as_int(mm));
        }
    }
}

// ---------------- quantization ----------------
__device__ __forceinline__ int quant1(float v, float invd) {
    int q = __float2int_rn(v * invd);
    q = max(-128, min(127, q));
    return q & 0xff;
}
__device__ __forceinline__ int pack4(float a, float b, float c, float d, float invd) {
    return quant1(a, invd) | (quant1(b, invd) << 8) |
           (quant1(c, invd) << 16) | (quant1(d, invd) << 24);
}

__global__ void quant_q_kernel() {
    int tid = blockIdx.x * blockDim.x + threadIdx.x;
    int dw = tid & 15;
    int n  = (tid >> 4) & (NQ - 1);
    int bh = tid >> 16;
    int b = bh >> 3, h = bh & 7;
    float invd = 127.0f / __int_as_float(g_maxbits[0]);
    float4 v = *(const float4*)(g_q + ((size_t)(b * NQ + n) * D + h * DH + dw * 4));
    g_q8[tid] = pack4(v.x, v.y, v.z, v.w, invd);
}
__global__ void quant_kT_kernel() {
    int tid = blockIdx.x * blockDim.x + threadIdx.x;
    int j  = tid & (NK - 1);
    int w  = (tid >> 10) & 15;
    int bh = tid >> 14;
    int b = bh >> 3, h = bh & 7;
    float invd = 127.0f / __int_as_float(g_maxbits[1]);
    float4 v = *(const float4*)(g_k + ((size_t)(b * NK + j) * D + h * DH + w * 4));
    g_k8t[tid] = pack4(v.x, v.y, v.z, v.w, invd);
}
__global__ void quant_vT_kernel() {
    int tid = blockIdx.x * blockDim.x + threadIdx.x;
    int d  = tid & 63;
    int w  = (tid >> 6) & 255;
    int bh = tid >> 14;
    int b = bh >> 3, h = bh & 7;
    float invd = 127.0f / __int_as_float(g_maxbits[2]);
    int j0 = w * 4;
    float v0 = g_v[(size_t)(b * NK + j0 + 0) * D + h * DH + d];
    float v1 = g_v[(size_t)(b * NK + j0 + 1) * D + h * DH + d];
    float v2 = g_v[(size_t)(b * NK + j0 + 2) * D + h * DH + d];
    float v3 = g_v[(size_t)(b * NK + j0 + 3) * D + h * DH + d];
    g_v8t[tid] = pack4(v0, v1, v2, v3, invd);
}

// ---------------- int8 mma.sync m16n8k32 ----------------
__device__ __forceinline__ void imma(int* c, int a0, int a1, int a2, int a3,
                                     int b0, int b1) {
    asm volatile(
        "mma.sync.aligned.m16n8k32.row.col.s32.s8.s8.s32 "
        "{%0,%1,%2,%3}, {%4,%5,%6,%7}, {%8,%9}, {%0,%1,%2,%3};"
        : "+r"(c[0]), "+r"(c[1]), "+r"(c[2]), "+r"(c[3])
        : "r"(a0), "r"(a1), "r"(a2), "r"(a3), "r"(b0), "r"(b1));
}

// ======== attention pass 1 (IMMA): scores, rowmax, p=exp, Z, global attn-max ========
#define K8S_STRIDE 1032
#define P1_SMEM (16 * K8S_STRIDE * 4)

__global__ __launch_bounds__(256) void attn_pass1() {
    extern __shared__ int k8s[];
    __shared__ float s_m[8];
    const int tid  = threadIdx.x;
    const int lane = tid & 31;
    const int warp = tid >> 5;
    const int bh   = blockIdx.y;
    const int Rw   = blockIdx.x * 128 + warp * 16;

    const int4* src = (const int4*)(g_k8t + (size_t)bh * 16 * NK);
    #pragma unroll
    for (int i = 0; i < 16; i++) {
        int idx = i * 256 + tid;
        int w  = idx >> 8;
        int j4 = idx & 255;
        *(int4*)(k8s + w * K8S_STRIDE + j4 * 4) = src[idx];
    }
    __syncthreads();

    const float dq = __int_as_float(g_maxbits[0]) * (1.0f / 127.0f);
    const float dk = __int_as_float(g_maxbits[1]) * (1.0f / 127.0f);
    const float alpha = dq * dk * 0.125f;

    const int r0 = Rw + (lane >> 2);
    const int* q0 = g_q8 + ((size_t)bh * NQ + r0) * 16;
    const int* q1 = q0 + 8 * 16;
    int a[2][4];
    #pragma unroll
    for (int ks = 0; ks < 2; ks++) {
        a[ks][0] = q0[ks * 8 + (lane & 3)];
        a[ks][1] = q1[ks * 8 + (lane & 3)];
        a[ks][2] = q0[ks * 8 + 4 + (lane & 3)];
        a[ks][3] = q1[ks * 8 + 4 + (lane & 3)];
    }

    int m0i = -2147483647, m1i = -2147483647;
    for (int jb = 0; jb < 128; jb++) {
        int c[4] = {0, 0, 0, 0};
        #pragma unroll
        for (int ks = 0; ks < 2; ks++) {
            int b0 = k8s[(ks * 8 + (lane & 3)) * K8S_STRIDE + jb * 8 + (lane >> 2)];
            int b1 = k8s[(ks * 8 + 4 + (lane & 3)) * K8S_STRIDE + jb * 8 + (lane >> 2)];
            imma(c, a[ks][0], a[ks][1], a[ks][2], a[ks][3], b0, b1);
        }
        m0i = max(m0i, max(c[0], c[1]));
        m1i = max(m1i, max(c[2], c[3]));
    }
    m0i = max(m0i, __shfl_xor_sync(0xffffffffu, m0i, 1));
    m0i = max(m0i, __shfl_xor_sync(0xffffffffu, m0i, 2));
    m1i = max(m1i, __shfl_xor_sync(0xffffffffu, m1i, 1));
    m1i = max(m1i, __shfl_xor_sync(0xffffffffu, m1i, 2));

    float* pr0 = g_p + ((size_t)bh * NQ + r0) * NK;
    float* pr1 = pr0 + (size_t)8 * NK;
    float z0 = 0.0f, z1 = 0.0f;
    for (int jb = 0; jb < 128; jb++) {
        int c[4] = {0, 0, 0, 0};
        #pragma unroll
        for (int ks = 0; ks < 2; ks++) {
            int b0 = k8s[(ks * 8 + (lane & 3)) * K8S_STRIDE + jb * 8 + (lane >> 2)];
            int b1 = k8s[(ks * 8 + 4 + (lane & 3)) * K8S_STRIDE + jb * 8 + (lane >> 2)];
            imma(c, a[ks][0], a[ks][1], a[ks][2], a[ks][3], b0, b1);
        }
        float e00 = __expf((float)(c[0] - m0i) * alpha);
        float e01 = __expf((float)(c[1] - m0i) * alpha);
        float e10 = __expf((float)(c[2] - m1i) * alpha);
        float e11 = __expf((float)(c[3] - m1i) * alpha);
        z0 += e00 + e01;
        z1 += e10 + e11;
        const int col = jb * 8 + 2 * (lane & 3);
        *(float2*)(pr0 + col) = make_float2(e00, e01);
        *(float2*)(pr1 + col) = make_float2(e10, e11);
    }
    z0 += __shfl_xor_sync(0xffffffffu, z0, 1);
    z0 += __shfl_xor_sync(0xffffffffu, z0, 2);
    z1 += __shfl_xor_sync(0xffffffffu, z1, 1);
    z1 += __shfl_xor_sync(0xffffffffu, z1, 2);

    if ((lane & 3) == 0) {
        g_rowz[(size_t)bh * NQ + r0]     = z0;
        g_rowz[(size_t)bh * NQ + r0 + 8] = z1;
    }
    float inv = fmaxf(1.0f / z0, 1.0f / z1);
    #pragma unroll
    for (int o = 16; o; o >>= 1) inv = fmaxf(inv, __shfl_xor_sync(0xffffffffu, inv, o));
    if (lane == 0) s_m[warp] = inv;
    __syncthreads();
    if (tid == 0) {
        float mm = s_m[0];
        #pragma unroll
        for (int i = 1; i < 8; i++) mm = fmaxf(mm, s_m[i]);
        atomicMax(&g_maxbits[3], __float_as_int(mm));
    }
}

// ======== attention pass 2 (IMMA): quantize stored p, int8 AV ========
#define V8S_STRIDE 260
#define AQ_STRIDE  68
#define P2_V_INTS  (64 * V8S_STRIDE)
#define P2_SMEM    ((P2_V_INTS + 8 * 16 * AQ_STRIDE) * 4)

__global__ __launch_bounds__(256) void attn_pass2() {
    extern __shared__ int sm2[];
    int* v8s = sm2;
    int* aqb = sm2 + P2_V_INTS;
    const int tid  = threadIdx.x;
    const int lane = tid & 31;
    const int warp = tid >> 5;
    const int bh   = blockIdx.y;
    const int Rw   = blockIdx.x * 128 + warp * 16;
    const int b = bh >> 3, h = bh & 7;

    const int* vsrc = g_v8t + (size_t)bh * 256 * DH;
    #pragma unroll
    for (int i = 0; i < 64; i++) {
        int idx = i * 256 + tid;
        int w = idx >> 6, d = idx & 63;
        v8s[d * V8S_STRIDE + w] = vsrc[idx];
    }
    __syncthreads();

    const float amax = __int_as_float(g_maxbits[3]);
    const float da   = amax * (1.0f / 127.0f);
    const float dv   = __int_as_float(g_maxbits[2]) * (1.0f / 127.0f);

    const int rloc = lane >> 1;
    const float rz = g_rowz[(size_t)bh * NQ + Rw + rloc];
    const float escale = (127.0f / amax) / rz;
    const float* prow = g_p + ((size_t)bh * NQ + Rw + rloc) * NK + (lane & 1) * 128;

    int acc[8][4];
    #pragma unroll
    for (int i = 0; i < 8; i++)
        #pragma unroll
        for (int j = 0; j < 4; j++) acc[i][j] = 0;

    int* aqw = aqb + warp * 16 * AQ_STRIDE;

    for (int ch = 0; ch < 4; ch++) {
        const float* pp = prow + ch * 256;
        int* dst = aqw + rloc * AQ_STRIDE + (lane & 1) * 32;
        #pragma unroll
        for (int g = 0; g < 32; g++) {
            float4 pv = *(const float4*)(pp + g * 4);
            int a0 = min(127, __float2int_rn(pv.x * escale));
            int a1 = min(127, __float2int_rn(pv.y * escale));
            int a2 = min(127, __float2int_rn(pv.z * escale));
            int a3 = min(127, __float2int_rn(pv.w * escale));
            dst[g] = a0 | (a1 << 8) | (a2 << 16) | (a3 << 24);
        }
        __syncwarp();

        #pragma unroll
        for (int js = 0; js < 8; js++) {
            int a0 = aqw[(lane >> 2) * AQ_STRIDE + js * 8 + (lane & 3)];
            int a1 = aqw[((lane >> 2) + 8) * AQ_STRIDE + js * 8 + (lane & 3)];
            int a2 = aqw[(lane >> 2) * AQ_STRIDE + js * 8 + 4 + (lane & 3)];
            int a3 = aqw[((lane >> 2) + 8) * AQ_STRIDE + js * 8 + 4 + (lane & 3)];
            const int wbase = ch * 64 + js * 8;
            #pragma unroll
            for (int db = 0; db < 8; db++) {
                int b0 = v8s[(db * 8 + (lane >> 2)) * V8S_STRIDE + wbase + (lane & 3)];
                int b1 = v8s[(db * 8 + (lane >> 2)) * V8S_STRIDE + wbase + 4 + (lane & 3)];
                imma(acc[db], a0, a1, a2, a3, b0, b1);
            }
        }
        __syncwarp();
    }

    const float oscale = da * dv;
    const int r = Rw + (lane >> 2);
    float* o0 = g_oattn + ((size_t)(b * NQ) + r) * D + h * DH;
    float* o1 = o0 + (size_t)8 * D;
    #pragma unroll
    for (int db = 0; db < 8; db++) {
        const int col = db * 8 + 2 * (lane & 3);
        *(float2*)(o0 + col) = make_float2((float)acc[db][0] * oscale,
                                           (float)acc[db][1] * oscale);
        *(float2*)(o1 + col) = make_float2((float)acc[db][2] * oscale,
                                           (float)acc[db][3] * oscale);
    }
}

// ================= launch =================
extern "C" void kernel_launch(void* const* d_in, const int* in_sizes, int n_in,
                              void* d_out, int out_size) {
    const float* x   = (const float*)d_in[0];
    const float* ctx = (const float*)d_in[1];
    const float* Wq  = (const float*)d_in[2];
    const float* Wk  = (const float*)d_in[3];
    const float* Wv  = (const float*)d_in[4];
    const float* Wo  = (const float*)d_in[5];
    const float* bo  = (const float*)d_in[6];
    float* out = (float*)d_out;

    void *pq, *pk, *pv, *po;
    cudaGetSymbolAddress(&pq, g_q);
    cudaGetSymbolAddress(&pk, g_k);
    cudaGetSymbolAddress(&pv, g_v);
    cudaGetSymbolAddress(&po, g_oattn);

    cudaFuncSetAttribute(gemm_bf3,   cudaFuncAttributeMaxDynamicSharedMemorySize, GB_SMEM);
    cudaFuncSetAttribute(attn_pass1, cudaFuncAttributeMaxDynamicSharedMemorySize, P1_SMEM);
    cudaFuncSetAttribute(attn_pass2, cudaFuncAttributeMaxDynamicSharedMemorySize, P2_SMEM);

    init_kernel<<<1, 32>>>();

    // projections on tensor pipe (2-split bf16, 3 products), absmax fused in epilogue
    gemm_bf3<<<dim3(D / 128, MQ / 128), 256, GB_SMEM>>>(
        x, Wq, nullptr, nullptr, (float*)pq, nullptr, MQ, D, D, 0);
    gemm_bf3<<<dim3(D / 128, MK / 128, 2), 256, GB_SMEM>>>(
        ctx, Wk, Wv, nullptr, (float*)pk, (float*)pv, MK, D, DC, 1);

    quant_q_kernel <<<(BH * NQ * 16) / 256, 256>>>();
    quant_kT_kernel<<<(BH * 16 * NK) / 256, 256>>>();
    quant_vT_kernel<<<(BH * 256 * DH) / 256, 256>>>();

    attn_pass1<<<dim3(NQ / 128, BH), 256, P1_SMEM>>>();
    attn_pass2<<<dim3(NQ / 128, BH), 256, P2_SMEM>>>();

    gemm_bf3<<<dim3(D / 128, MQ / 128), 256, GB_SMEM>>>(
        (const float*)po, Wo, nullptr, bo, out, nullptr, MQ, D, D, -1);
}